// round 12
// baseline (speedup 1.0000x reference)
#include <cuda_runtime.h>
#include <cuda_fp16.h>
#include <cstdint>

#define B_   2
#define S_   2048
#define H_   8
#define DH_  64
#define DM_  512
#define BH_  (B_*H_)
#define MTOT (B_*S_)   // 4096

// exp(s/8) = exp2(s * 0.125 * log2(e)); folded into Q at qkv epilogue
#define EXP_C 0.18033688011112042f

// fp16 fragment-order scratch (uint32 = 2 halves)
__device__ uint32_t g_xF16u[256*32*128];
__device__ uint32_t g_WF16u[4*32*32*128];
__device__ uint32_t g_OF16u[256*32*128];
__device__ uint16_t g_QF16[16*128*4*256];
__device__ uint16_t g_KF16[16*32*4*4*256];
__device__ uint16_t g_VF16[16*32*4*4*256];

__device__ __forceinline__ float ex2f(float x) {
    float r;
    asm("ex2.approx.ftz.f32 %0, %1;" : "=f"(r) : "f"(x));
    return r;
}
__device__ __forceinline__ uint32_t packh2(float lo, float hi) {
    uint32_t r;
    asm("cvt.rn.f16x2.f32 %0, %1, %2;" : "=r"(r) : "f"(hi), "f"(lo));
    return r;
}
__device__ __forceinline__ void mma16(float4& d, const uint4& a, uint32_t b0, uint32_t b1) {
    asm volatile(
        "mma.sync.aligned.m16n8k16.row.col.f32.f16.f16.f32 "
        "{%0,%1,%2,%3}, {%4,%5,%6,%7}, {%8,%9}, {%0,%1,%2,%3};"
        : "+f"(d.x), "+f"(d.y), "+f"(d.z), "+f"(d.w)
        : "r"(a.x), "r"(a.y), "r"(a.z), "r"(a.w), "r"(b0), "r"(b1));
}
__device__ __forceinline__ void cpa16(uint32_t smem, const void* gmem) {
    asm volatile("cp.async.cg.shared.global [%0], [%1], 16;" :: "r"(smem), "l"(gmem));
}
__device__ __forceinline__ void cpa_commit() {
    asm volatile("cp.async.commit_group;");
}
template<int N> __device__ __forceinline__ void cpa_wait() {
    asm volatile("cp.async.wait_group %0;" :: "n"(N));
}

// ---------------------------------------------------------------------------
// Transform: x -> fp16 A-frags
// ---------------------------------------------------------------------------
__global__ __launch_bounds__(256) void x_transform_kernel(const float* __restrict__ x)
{
    const int task = blockIdx.x * 8 + (threadIdx.x >> 5);
    const int lane = threadIdx.x & 31;
    const int rt = task >> 5, ks = task & 31;
    const int r0 = rt*16 + (lane >> 2);
    const int k0 = ks*16 + 2*(lane & 3);
    float2 a = *(const float2*)&x[(size_t)r0*DM_ + k0];
    float2 b = *(const float2*)&x[(size_t)(r0+8)*DM_ + k0];
    float2 c = *(const float2*)&x[(size_t)r0*DM_ + k0 + 8];
    float2 d = *(const float2*)&x[(size_t)(r0+8)*DM_ + k0 + 8];
    uint4 v;
    v.x = packh2(a.x, a.y);
    v.y = packh2(b.x, b.y);
    v.z = packh2(c.x, c.y);
    v.w = packh2(d.x, d.y);
    *(uint4*)&g_xF16u[(size_t)task*128 + lane*4] = v;
}

// ---------------------------------------------------------------------------
// Transform: W -> paired fp16 B-frags
// ---------------------------------------------------------------------------
__global__ __launch_bounds__(256) void w_transform_kernel(
    const float* __restrict__ Wq, const float* __restrict__ Wk,
    const float* __restrict__ Wv, const float* __restrict__ Wo)
{
    const int task = blockIdx.x * 8 + (threadIdx.x >> 5);
    const int lane = threadIdx.x & 31;
    const int z = task >> 10, ks = (task >> 5) & 31, np = task & 31;
    const int k0 = ks*16 + 2*(lane & 3);
    const int n0 = np*16 + (lane >> 2);

    auto ldw = [&](int k, int n) -> float {
        if (z == 3) return Wo[(size_t)k*DM_ + n];
        const float* Wz = (z == 0) ? Wq : (z == 1) ? Wk : Wv;
        return Wz[((size_t)(n >> 6)*DM_ + k)*DH_ + (n & 63)];
    };
    uint4 v;
    v.x = packh2(ldw(k0,   n0),   ldw(k0+1, n0));
    v.y = packh2(ldw(k0+8, n0),   ldw(k0+9, n0));
    v.z = packh2(ldw(k0,   n0+8), ldw(k0+1, n0+8));
    v.w = packh2(ldw(k0+8, n0+8), ldw(k0+9, n0+8));
    *(uint4*)&g_WF16u[(size_t)task*128 + lane*4] = v;
}

// ---------------------------------------------------------------------------
// QKV fp16 frag-order scatter. Q gets EXP_C folded in.
// ---------------------------------------------------------------------------
__device__ __forceinline__ void store_qkv16(int z, float val, int row, int col)
{
    int b = row >> 11, s = row & (S_-1);
    int h = col >> 6, d = col & 63;
    int bh = b*8 + h;
    if (z == 0) val *= EXP_C;
    uint16_t hv = __half_as_ushort(__float2half_rn(val));
    if (z == 0) {
        int qtile = s >> 4, r = s & 15, dstep = d >> 4, k = d & 15;
        int lane = (r & 7)*4 + ((k & 7) >> 1);
        int reg  = ((r >> 3) & 1) + (((k >> 3) & 1) << 1);
        size_t u32i = (((size_t)(bh*128 + qtile))*4 + dstep)*128 + lane*4 + reg;
        g_QF16[u32i*2 + (k & 1)] = hv;
    } else if (z == 1) {
        int kt = s >> 6, nt = (s & 63) >> 3, n = s & 7, dstep = d >> 4, k = d & 15;
        int lane = n*4 + ((k & 7) >> 1);
        size_t u32i = ((((size_t)(bh*32 + kt))*4 + dstep)*4 + (nt >> 1))*128
                    + lane*4 + (nt & 1)*2 + ((k >> 3) & 1);
        g_KF16[u32i*2 + (k & 1)] = hv;
    } else {
        int kt = s >> 6, kstep = (s & 63) >> 4, k = s & 15, nt = d >> 3, n = d & 7;
        int lane = n*4 + ((k & 7) >> 1);
        size_t u32i = ((((size_t)(bh*32 + kt))*4 + kstep)*4 + (nt >> 1))*128
                    + lane*4 + (nt & 1)*2 + ((k >> 3) & 1);
        g_VF16[u32i*2 + (k & 1)] = hv;
    }
}

// ---------------------------------------------------------------------------
// fp16 GEMM mainloop: 3-stage cp.async ring, ONE sync per chunk.
// ---------------------------------------------------------------------------
#define GEMM_SMEM_BYTES (3*16384)   // 48 KB

template<typename EpiF>
__device__ __forceinline__ void gemm16_body(
    const uint32_t* __restrict__ Asrc,
    const uint32_t* __restrict__ Bsrc,
    int rt0, int np0, EpiF epi)
{
    extern __shared__ float smf[];
    uint32_t* smu = (uint32_t*)smf;
    const uint32_t sbase = (uint32_t)__cvta_generic_to_shared(smf);

    const int tid  = threadIdx.x;
    const int lane = tid & 31;
    const int wid  = tid >> 5;
    const int wm   = wid >> 2, wn = wid & 3;

    float4 c[4][4];
    #pragma unroll
    for (int i = 0; i < 4; i++)
        #pragma unroll
        for (int j = 0; j < 4; j++) c[i][j] = make_float4(0.f,0.f,0.f,0.f);

    auto stage = [&](int chunk, int st) {
        const int ks0 = chunk * 2;
        const uint32_t s0 = sbase + (uint32_t)(st * 16384);
        #pragma unroll
        for (int c2 = 0; c2 < 2; c2++) {
            int seg = tid + 256*c2;
            int bb = seg >> 5, w = seg & 31;
            cpa16(s0 + (uint32_t)seg*16,
                  &Asrc[((size_t)(rt0 + (bb & 7))*32 + ks0 + (bb >> 3))*128 + w*4]);
        }
        #pragma unroll
        for (int c2 = 0; c2 < 2; c2++) {
            int seg = tid + 256*c2;
            int bb = seg >> 5, w = seg & 31;
            cpa16(s0 + 8192 + (uint32_t)seg*16,
                  &Bsrc[((size_t)(ks0 + (bb >> 3))*32 + np0 + (bb & 7))*128 + w*4]);
        }
        cpa_commit();
    };

    stage(0, 0);
    stage(1, 1);
    for (int ch = 0; ch < 16; ch++) {
        if (ch < 15) cpa_wait<1>(); else cpa_wait<0>();
        __syncthreads();
        if (ch + 2 < 16) stage(ch + 2, (ch + 2) % 3);
        const uint32_t* As = smu + (ch % 3) * 4096;
        const uint32_t* Bs = As + 2048;
        #pragma unroll
        for (int step = 0; step < 2; step++) {
            uint4 af[4];
            #pragma unroll
            for (int mt = 0; mt < 4; mt++)
                af[mt] = *(const uint4*)&As[(step*8 + wm*4 + mt)*128 + lane*4];
            #pragma unroll
            for (int np = 0; np < 2; np++) {
                uint4 bb = *(const uint4*)&Bs[(step*8 + wn*2 + np)*128 + lane*4];
                #pragma unroll
                for (int mt = 0; mt < 4; mt++) {
                    mma16(c[mt][2*np],   af[mt], bb.x, bb.y);
                    mma16(c[mt][2*np+1], af[mt], bb.z, bb.w);
                }
            }
        }
    }
    epi(c, wm, wn, lane);
}

__global__ __launch_bounds__(256, 2) void qkv_proj_kernel(
    const float* __restrict__ bq, const float* __restrict__ bk, const float* __restrict__ bv)
{
    const int z  = blockIdx.z;
    const float* bias = (z == 0) ? bq : (z == 1) ? bk : bv;
    const int n0 = blockIdx.x * 128;
    const int m0 = blockIdx.y * 128;

    gemm16_body(g_xF16u, &g_WF16u[(size_t)z*32*32*128], m0 >> 4, n0 >> 4,
        [&](float4 (&c)[4][4], int wm, int wn, int lane) {
            const int g = lane >> 2, t = lane & 3;
            #pragma unroll
            for (int mt = 0; mt < 4; mt++) {
                int r1 = m0 + wm*64 + mt*16 + g;
                #pragma unroll
                for (int nt = 0; nt < 4; nt++) {
                    int c1 = n0 + wn*32 + nt*8 + 2*t;
                    float b0 = bias[c1], b1 = bias[c1+1];
                    store_qkv16(z, c[mt][nt].x + b0, r1,   c1);
                    store_qkv16(z, c[mt][nt].y + b1, r1,   c1+1);
                    store_qkv16(z, c[mt][nt].z + b0, r1+8, c1);
                    store_qkv16(z, c[mt][nt].w + b1, r1+8, c1+1);
                }
            }
        });
}

__global__ __launch_bounds__(256, 2) void out_proj_kernel(
    const float* __restrict__ bo, float* __restrict__ out)
{
    const int n0 = blockIdx.x * 128;
    const int m0 = blockIdx.y * 128;

    gemm16_body(g_OF16u, &g_WF16u[(size_t)3*32*32*128], m0 >> 4, n0 >> 4,
        [&](float4 (&c)[4][4], int wm, int wn, int lane) {
            const int g = lane >> 2, t = lane & 3;
            #pragma unroll
            for (int mt = 0; mt < 4; mt++) {
                int mlo = m0 + wm*64 + mt*16 + g;
                int mhi = mlo + 8;
                #pragma unroll
                for (int nt = 0; nt < 4; nt++) {
                    int col = n0 + wn*32 + nt*8 + 2*t;
                    float b0 = bo[col], b1 = bo[col+1];
                    *(float2*)&out[(size_t)mlo*DM_ + col] =
                        make_float2(c[mt][nt].x + b0, c[mt][nt].y + b1);
                    *(float2*)&out[(size_t)mhi*DM_ + col] =
                        make_float2(c[mt][nt].z + b0, c[mt][nt].w + b1);
                }
            }
        });
}

// ---------------------------------------------------------------------------
// Flash attention: fp16 k16, paired B-frags, EXP_C pre-folded into Q,
// tensor-core row sums (ones column), 3-stage ring with ONE sync per tile.
// ---------------------------------------------------------------------------
#define ATTN_SMEM_BYTES (3*16384)   // 48 KB

__global__ __launch_bounds__(256, 2) void attn_kernel()
{
    extern __shared__ float smf[];
    uint32_t* smu = (uint32_t*)smf;
    const uint32_t sbase = (uint32_t)__cvta_generic_to_shared(smf);

    const int tid  = threadIdx.x;
    const int lane = tid & 31;
    const int wid  = tid >> 5;
    const int q0 = blockIdx.x * 128;
    const int bh = blockIdx.y;
    const int b  = bh >> 3, h = bh & 7;

    uint4 qf[4];
    {
        const uint32_t* QFu = (const uint32_t*)g_QF16;
        const size_t qbase = ((size_t)(bh*128 + (q0>>4) + wid)) * 4 * 128;
        #pragma unroll
        for (int step = 0; step < 4; step++)
            qf[step] = *(const uint4*)&QFu[qbase + step*128 + lane*4];
    }

    float4 o[8];
    #pragma unroll
    for (int nt = 0; nt < 8; nt++) o[nt] = make_float4(0.f,0.f,0.f,0.f);
    float4 osum = make_float4(0.f,0.f,0.f,0.f);
    // ones column B-frag: B[k][0] = 1, other columns 0
    const uint32_t ones_b = (lane < 4) ? 0x3C003C00u : 0u;

    const uint32_t* KFu = (const uint32_t*)g_KF16 + (size_t)bh*32*2048;
    const uint32_t* VFu = (const uint32_t*)g_VF16 + (size_t)bh*32*2048;

    auto stage = [&](int kt, int st) {
        const uint32_t s0 = sbase + (uint32_t)(st * 16384);
        const uint32_t* Ksrc = KFu + (size_t)kt * 2048;
        const uint32_t* Vsrc = VFu + (size_t)kt * 2048;
        #pragma unroll
        for (int c2 = 0; c2 < 2; c2++) {
            int seg = tid + 256*c2;
            cpa16(s0 + (uint32_t)seg*16,        Ksrc + seg*4);
            cpa16(s0 + 8192 + (uint32_t)seg*16, Vsrc + seg*4);
        }
        cpa_commit();
    };

    stage(0, 0);
    stage(1, 1);
    for (int kt = 0; kt < 32; kt++) {
        if (kt < 31) cpa_wait<1>(); else cpa_wait<0>();
        __syncthreads();
        if (kt + 2 < 32) stage(kt + 2, (kt + 2) % 3);
        const uint32_t* Ks = smu + (kt % 3) * 4096;
        const uint32_t* Vs = Ks + 2048;

        // S = Q K^T (Q pre-scaled by EXP_C)
        float4 s[8];
        #pragma unroll
        for (int nt = 0; nt < 8; nt++) s[nt] = make_float4(0.f,0.f,0.f,0.f);
        #pragma unroll
        for (int step = 0; step < 4; step++) {
            #pragma unroll
            for (int np = 0; np < 4; np++) {
                uint4 kk = *(const uint4*)&Ks[(step*4 + np)*128 + lane*4];
                mma16(s[2*np],   qf[step], kk.x, kk.y);
                mma16(s[2*np+1], qf[step], kk.z, kk.w);
            }
        }

        // p = exp2(s) directly (scale folded into Q); no scalar row sums
        #pragma unroll
        for (int nt = 0; nt < 8; nt++) {
            s[nt].x = ex2f(s[nt].x);
            s[nt].y = ex2f(s[nt].y);
            s[nt].z = ex2f(s[nt].z);
            s[nt].w = ex2f(s[nt].w);
        }

        // FA2 identity: pack C-frag pairs -> A-frag of k16 fp16 mma
        uint4 pa[4];
        #pragma unroll
        for (int j = 0; j < 4; j++) {
            pa[j].x = packh2(s[2*j].x,   s[2*j].y);
            pa[j].y = packh2(s[2*j].z,   s[2*j].w);
            pa[j].z = packh2(s[2*j+1].x, s[2*j+1].y);
            pa[j].w = packh2(s[2*j+1].z, s[2*j+1].w);
        }

        // row sums via tensor core (ones column); exact fp32
        #pragma unroll
        for (int j = 0; j < 4; j++)
            mma16(osum, pa[j], ones_b, ones_b);

        // O += P V
        #pragma unroll
        for (int j = 0; j < 4; j++) {
            #pragma unroll
            for (int np = 0; np < 4; np++) {
                uint4 vv = *(const uint4*)&Vs[(j*4 + np)*128 + lane*4];
                mma16(o[2*np],   pa[j], vv.x, vv.y);
                mma16(o[2*np+1], pa[j], vv.z, vv.w);
            }
        }
    }

    // broadcast row sums from quad lane 0 (column 0 of osum)
    const float llo = __shfl_sync(0xffffffffu, osum.x, (lane >> 2) * 4);
    const float lhi = __shfl_sync(0xffffffffu, osum.z, (lane >> 2) * 4);
    const float ilo = 1.f / llo, ihi = 1.f / lhi;

    // epilogue: scale + FA2 pack -> fp16 A-frags of OF
    const int rowtile = b*128 + (q0>>4) + wid;
    #pragma unroll
    for (int j = 0; j < 4; j++) {
        uint4 ov;
        ov.x = packh2(o[2*j].x   * ilo, o[2*j].y   * ilo);
        ov.y = packh2(o[2*j].z   * ihi, o[2*j].w   * ihi);
        ov.z = packh2(o[2*j+1].x * ilo, o[2*j+1].y * ilo);
        ov.w = packh2(o[2*j+1].z * ihi, o[2*j+1].w * ihi);
        *(uint4*)&g_OF16u[((size_t)rowtile*32 + h*4 + j)*128 + lane*4] = ov;
    }
}

// ---------------------------------------------------------------------------
extern "C" void kernel_launch(void* const* d_in, const int* in_sizes, int n_in,
                              void* d_out, int out_size)
{
    const float* x  = (const float*)d_in[0];
    const float* Wq = (const float*)d_in[1];
    const float* Wk = (const float*)d_in[2];
    const float* Wv = (const float*)d_in[3];
    const float* bq = (const float*)d_in[4];
    const float* bk = (const float*)d_in[5];
    const float* bv = (const float*)d_in[6];
    const float* Wo = (const float*)d_in[7];
    const float* bo = (const float*)d_in[8];
    float* out = (float*)d_out;

    (void)in_sizes; (void)n_in; (void)out_size;

    static int smem_set = 0;
    if (!smem_set) {
        cudaFuncSetAttribute(qkv_proj_kernel,
            cudaFuncAttributeMaxDynamicSharedMemorySize, GEMM_SMEM_BYTES);
        cudaFuncSetAttribute(attn_kernel,
            cudaFuncAttributeMaxDynamicSharedMemorySize, ATTN_SMEM_BYTES);
        cudaFuncSetAttribute(out_proj_kernel,
            cudaFuncAttributeMaxDynamicSharedMemorySize, GEMM_SMEM_BYTES);
        smem_set = 1;
    }

    x_transform_kernel<<<1024, 256>>>(x);
    w_transform_kernel<<<512, 256>>>(Wq, Wk, Wv, Wo);
    qkv_proj_kernel<<<dim3(DM_/128, MTOT/128, 3), 256, GEMM_SMEM_BYTES>>>(bq, bk, bv);
    attn_kernel<<<dim3(S_/128, BH_), 256, ATTN_SMEM_BYTES>>>();
    out_proj_kernel<<<dim3(DM_/128, MTOT/128), 256, GEMM_SMEM_BYTES>>>(bo, out);
}

// round 13
// speedup vs baseline: 1.0122x; 1.0122x over previous
#include <cuda_runtime.h>
#include <cuda_fp16.h>
#include <cstdint>

#define B_   2
#define S_   2048
#define H_   8
#define DH_  64
#define DM_  512
#define BH_  (B_*H_)
#define MTOT (B_*S_)   // 4096

// exp(s/8) = exp2(s * 0.125 * log2(e)); folded into Q at qkv epilogue
#define EXP_C 0.18033688011112042f

// fp16 fragment-order scratch (uint32 = 2 halves)
__device__ uint32_t g_xF16u[256*32*128];
__device__ uint32_t g_WF16u[4*32*32*128];
__device__ uint32_t g_OF16u[256*32*128];
__device__ uint16_t g_QF16[16*128*4*256];
__device__ uint16_t g_KF16[16*32*4*4*256];
__device__ uint16_t g_VF16[16*32*4*4*256];

__device__ __forceinline__ uint32_t packh2(float lo, float hi) {
    uint32_t r;
    asm("cvt.rn.f16x2.f32 %0, %1, %2;" : "=r"(r) : "f"(hi), "f"(lo));
    return r;
}
__device__ __forceinline__ uint32_t h2ex2(uint32_t x) {
    uint32_t r;
    asm("ex2.approx.f16x2 %0, %1;" : "=r"(r) : "r"(x));
    return r;
}
__device__ __forceinline__ void mma16(float4& d, const uint4& a, uint32_t b0, uint32_t b1) {
    asm volatile(
        "mma.sync.aligned.m16n8k16.row.col.f32.f16.f16.f32 "
        "{%0,%1,%2,%3}, {%4,%5,%6,%7}, {%8,%9}, {%0,%1,%2,%3};"
        : "+f"(d.x), "+f"(d.y), "+f"(d.z), "+f"(d.w)
        : "r"(a.x), "r"(a.y), "r"(a.z), "r"(a.w), "r"(b0), "r"(b1));
}
__device__ __forceinline__ void cpa16(uint32_t smem, const void* gmem) {
    asm volatile("cp.async.cg.shared.global [%0], [%1], 16;" :: "r"(smem), "l"(gmem));
}
__device__ __forceinline__ void cpa_commit() {
    asm volatile("cp.async.commit_group;");
}
template<int N> __device__ __forceinline__ void cpa_wait() {
    asm volatile("cp.async.wait_group %0;" :: "n"(N));
}

// ---------------------------------------------------------------------------
// Merged transform: x -> A-frags (tasks 0..8191), W -> paired B-frags (8192..12287)
// ---------------------------------------------------------------------------
__global__ __launch_bounds__(256) void xw_transform_kernel(
    const float* __restrict__ x,
    const float* __restrict__ Wq, const float* __restrict__ Wk,
    const float* __restrict__ Wv, const float* __restrict__ Wo)
{
    const int task = blockIdx.x * 8 + (threadIdx.x >> 5);
    const int lane = threadIdx.x & 31;
    if (task < 8192) {
        const int rt = task >> 5, ks = task & 31;
        const int r0 = rt*16 + (lane >> 2);
        const int k0 = ks*16 + 2*(lane & 3);
        float2 a = *(const float2*)&x[(size_t)r0*DM_ + k0];
        float2 b = *(const float2*)&x[(size_t)(r0+8)*DM_ + k0];
        float2 c = *(const float2*)&x[(size_t)r0*DM_ + k0 + 8];
        float2 d = *(const float2*)&x[(size_t)(r0+8)*DM_ + k0 + 8];
        uint4 v;
        v.x = packh2(a.x, a.y);
        v.y = packh2(b.x, b.y);
        v.z = packh2(c.x, c.y);
        v.w = packh2(d.x, d.y);
        *(uint4*)&g_xF16u[(size_t)task*128 + lane*4] = v;
    } else {
        const int wtask = task - 8192;
        const int z = wtask >> 10, ks = (wtask >> 5) & 31, np = wtask & 31;
        const int k0 = ks*16 + 2*(lane & 3);
        const int n0 = np*16 + (lane >> 2);
        auto ldw = [&](int k, int n) -> float {
            if (z == 3) return Wo[(size_t)k*DM_ + n];
            const float* Wz = (z == 0) ? Wq : (z == 1) ? Wk : Wv;
            return Wz[((size_t)(n >> 6)*DM_ + k)*DH_ + (n & 63)];
        };
        uint4 v;
        v.x = packh2(ldw(k0,   n0),   ldw(k0+1, n0));
        v.y = packh2(ldw(k0+8, n0),   ldw(k0+9, n0));
        v.z = packh2(ldw(k0,   n0+8), ldw(k0+1, n0+8));
        v.w = packh2(ldw(k0+8, n0+8), ldw(k0+9, n0+8));
        *(uint4*)&g_WF16u[(size_t)wtask*128 + lane*4] = v;
    }
}

// ---------------------------------------------------------------------------
// QKV fp16 frag-order scatter. Q gets EXP_C folded in.
// ---------------------------------------------------------------------------
__device__ __forceinline__ void store_qkv16(int z, float val, int row, int col)
{
    int b = row >> 11, s = row & (S_-1);
    int h = col >> 6, d = col & 63;
    int bh = b*8 + h;
    if (z == 0) val *= EXP_C;
    uint16_t hv = __half_as_ushort(__float2half_rn(val));
    if (z == 0) {
        int qtile = s >> 4, r = s & 15, dstep = d >> 4, k = d & 15;
        int lane = (r & 7)*4 + ((k & 7) >> 1);
        int reg  = ((r >> 3) & 1) + (((k >> 3) & 1) << 1);
        size_t u32i = (((size_t)(bh*128 + qtile))*4 + dstep)*128 + lane*4 + reg;
        g_QF16[u32i*2 + (k & 1)] = hv;
    } else if (z == 1) {
        int kt = s >> 6, nt = (s & 63) >> 3, n = s & 7, dstep = d >> 4, k = d & 15;
        int lane = n*4 + ((k & 7) >> 1);
        size_t u32i = ((((size_t)(bh*32 + kt))*4 + dstep)*4 + (nt >> 1))*128
                    + lane*4 + (nt & 1)*2 + ((k >> 3) & 1);
        g_KF16[u32i*2 + (k & 1)] = hv;
    } else {
        int kt = s >> 6, kstep = (s & 63) >> 4, k = s & 15, nt = d >> 3, n = d & 7;
        int lane = n*4 + ((k & 7) >> 1);
        size_t u32i = ((((size_t)(bh*32 + kt))*4 + kstep)*4 + (nt >> 1))*128
                    + lane*4 + (nt & 1)*2 + ((k >> 3) & 1);
        g_VF16[u32i*2 + (k & 1)] = hv;
    }
}

// ---------------------------------------------------------------------------
// fp16 GEMM mainloop: 3-stage cp.async ring, ONE sync per chunk.
// ---------------------------------------------------------------------------
#define GEMM_SMEM_BYTES (3*16384)   // 48 KB

template<typename EpiF>
__device__ __forceinline__ void gemm16_body(
    const uint32_t* __restrict__ Asrc,
    const uint32_t* __restrict__ Bsrc,
    int rt0, int np0, EpiF epi)
{
    extern __shared__ float smf[];
    uint32_t* smu = (uint32_t*)smf;
    const uint32_t sbase = (uint32_t)__cvta_generic_to_shared(smf);

    const int tid  = threadIdx.x;
    const int lane = tid & 31;
    const int wid  = tid >> 5;
    const int wm   = wid >> 2, wn = wid & 3;

    float4 c[4][4];
    #pragma unroll
    for (int i = 0; i < 4; i++)
        #pragma unroll
        for (int j = 0; j < 4; j++) c[i][j] = make_float4(0.f,0.f,0.f,0.f);

    auto stage = [&](int chunk, int st) {
        const int ks0 = chunk * 2;
        const uint32_t s0 = sbase + (uint32_t)(st * 16384);
        #pragma unroll
        for (int c2 = 0; c2 < 2; c2++) {
            int seg = tid + 256*c2;
            int bb = seg >> 5, w = seg & 31;
            cpa16(s0 + (uint32_t)seg*16,
                  &Asrc[((size_t)(rt0 + (bb & 7))*32 + ks0 + (bb >> 3))*128 + w*4]);
        }
        #pragma unroll
        for (int c2 = 0; c2 < 2; c2++) {
            int seg = tid + 256*c2;
            int bb = seg >> 5, w = seg & 31;
            cpa16(s0 + 8192 + (uint32_t)seg*16,
                  &Bsrc[((size_t)(ks0 + (bb >> 3))*32 + np0 + (bb & 7))*128 + w*4]);
        }
        cpa_commit();
    };

    stage(0, 0);
    stage(1, 1);
    for (int ch = 0; ch < 16; ch++) {
        if (ch < 15) cpa_wait<1>(); else cpa_wait<0>();
        __syncthreads();
        if (ch + 2 < 16) stage(ch + 2, (ch + 2) % 3);
        const uint32_t* As = smu + (ch % 3) * 4096;
        const uint32_t* Bs = As + 2048;
        #pragma unroll
        for (int step = 0; step < 2; step++) {
            uint4 af[4];
            #pragma unroll
            for (int mt = 0; mt < 4; mt++)
                af[mt] = *(const uint4*)&As[(step*8 + wm*4 + mt)*128 + lane*4];
            #pragma unroll
            for (int np = 0; np < 2; np++) {
                uint4 bb = *(const uint4*)&Bs[(step*8 + wn*2 + np)*128 + lane*4];
                #pragma unroll
                for (int mt = 0; mt < 4; mt++) {
                    mma16(c[mt][2*np],   af[mt], bb.x, bb.y);
                    mma16(c[mt][2*np+1], af[mt], bb.z, bb.w);
                }
            }
        }
    }
    epi(c, wm, wn, lane);
}

__global__ __launch_bounds__(256, 2) void qkv_proj_kernel(
    const float* __restrict__ bq, const float* __restrict__ bk, const float* __restrict__ bv)
{
    const int z  = blockIdx.z;
    const float* bias = (z == 0) ? bq : (z == 1) ? bk : bv;
    const int n0 = blockIdx.x * 128;
    const int m0 = blockIdx.y * 128;

    gemm16_body(g_xF16u, &g_WF16u[(size_t)z*32*32*128], m0 >> 4, n0 >> 4,
        [&](float4 (&c)[4][4], int wm, int wn, int lane) {
            const int g = lane >> 2, t = lane & 3;
            #pragma unroll
            for (int mt = 0; mt < 4; mt++) {
                int r1 = m0 + wm*64 + mt*16 + g;
                #pragma unroll
                for (int nt = 0; nt < 4; nt++) {
                    int c1 = n0 + wn*32 + nt*8 + 2*t;
                    float b0 = bias[c1], b1 = bias[c1+1];
                    store_qkv16(z, c[mt][nt].x + b0, r1,   c1);
                    store_qkv16(z, c[mt][nt].y + b1, r1,   c1+1);
                    store_qkv16(z, c[mt][nt].z + b0, r1+8, c1);
                    store_qkv16(z, c[mt][nt].w + b1, r1+8, c1+1);
                }
            }
        });
}

__global__ __launch_bounds__(256, 2) void out_proj_kernel(
    const float* __restrict__ bo, float* __restrict__ out)
{
    const int n0 = blockIdx.x * 128;
    const int m0 = blockIdx.y * 128;

    gemm16_body(g_OF16u, &g_WF16u[(size_t)3*32*32*128], m0 >> 4, n0 >> 4,
        [&](float4 (&c)[4][4], int wm, int wn, int lane) {
            const int g = lane >> 2, t = lane & 3;
            #pragma unroll
            for (int mt = 0; mt < 4; mt++) {
                int mlo = m0 + wm*64 + mt*16 + g;
                int mhi = mlo + 8;
                #pragma unroll
                for (int nt = 0; nt < 4; nt++) {
                    int col = n0 + wn*32 + nt*8 + 2*t;
                    float b0 = bo[col], b1 = bo[col+1];
                    *(float2*)&out[(size_t)mlo*DM_ + col] =
                        make_float2(c[mt][nt].x + b0, c[mt][nt].y + b1);
                    *(float2*)&out[(size_t)mhi*DM_ + col] =
                        make_float2(c[mt][nt].z + b0, c[mt][nt].w + b1);
                }
            }
        });
}

// ---------------------------------------------------------------------------
// Flash attention: fp16 k16, paired B-frags, EXP_C pre-folded into Q,
// fp16x2 exp (pack-then-ex2), tensor-core row sums, 3-stage ring.
// ---------------------------------------------------------------------------
#define ATTN_SMEM_BYTES (3*16384)   // 48 KB

__global__ __launch_bounds__(256, 2) void attn_kernel()
{
    extern __shared__ float smf[];
    uint32_t* smu = (uint32_t*)smf;
    const uint32_t sbase = (uint32_t)__cvta_generic_to_shared(smf);

    const int tid  = threadIdx.x;
    const int lane = tid & 31;
    const int wid  = tid >> 5;
    const int q0 = blockIdx.x * 128;
    const int bh = blockIdx.y;
    const int b  = bh >> 3, h = bh & 7;

    uint4 qf[4];
    {
        const uint32_t* QFu = (const uint32_t*)g_QF16;
        const size_t qbase = ((size_t)(bh*128 + (q0>>4) + wid)) * 4 * 128;
        #pragma unroll
        for (int step = 0; step < 4; step++)
            qf[step] = *(const uint4*)&QFu[qbase + step*128 + lane*4];
    }

    float4 o[8];
    #pragma unroll
    for (int nt = 0; nt < 8; nt++) o[nt] = make_float4(0.f,0.f,0.f,0.f);
    float4 osum = make_float4(0.f,0.f,0.f,0.f);
    const uint32_t ones_b = (lane < 4) ? 0x3C003C00u : 0u;

    const uint32_t* KFu = (const uint32_t*)g_KF16 + (size_t)bh*32*2048;
    const uint32_t* VFu = (const uint32_t*)g_VF16 + (size_t)bh*32*2048;

    auto stage = [&](int kt, int st) {
        const uint32_t s0 = sbase + (uint32_t)(st * 16384);
        const uint32_t* Ksrc = KFu + (size_t)kt * 2048;
        const uint32_t* Vsrc = VFu + (size_t)kt * 2048;
        #pragma unroll
        for (int c2 = 0; c2 < 2; c2++) {
            int seg = tid + 256*c2;
            cpa16(s0 + (uint32_t)seg*16,        Ksrc + seg*4);
            cpa16(s0 + 8192 + (uint32_t)seg*16, Vsrc + seg*4);
        }
        cpa_commit();
    };

    stage(0, 0);
    stage(1, 1);
    for (int kt = 0; kt < 32; kt++) {
        if (kt < 31) cpa_wait<1>(); else cpa_wait<0>();
        __syncthreads();
        if (kt + 2 < 32) stage(kt + 2, (kt + 2) % 3);
        const uint32_t* Ks = smu + (kt % 3) * 4096;
        const uint32_t* Vs = Ks + 2048;

        // S = Q K^T (Q pre-scaled by EXP_C -> S is log2-domain)
        float4 s[8];
        #pragma unroll
        for (int nt = 0; nt < 8; nt++) s[nt] = make_float4(0.f,0.f,0.f,0.f);
        #pragma unroll
        for (int step = 0; step < 4; step++) {
            #pragma unroll
            for (int np = 0; np < 4; np++) {
                uint4 kk = *(const uint4*)&Ks[(step*4 + np)*128 + lane*4];
                mma16(s[2*np],   qf[step], kk.x, kk.y);
                mma16(s[2*np+1], qf[step], kk.z, kk.w);
            }
        }

        // pack s (fp16x2), then exp2 in fp16x2 -> P A-frags directly.
        // Halves MUFU ops vs per-float ex2.f32.
        uint4 pa[4];
        #pragma unroll
        for (int j = 0; j < 4; j++) {
            pa[j].x = h2ex2(packh2(s[2*j].x,   s[2*j].y));
            pa[j].y = h2ex2(packh2(s[2*j].z,   s[2*j].w));
            pa[j].z = h2ex2(packh2(s[2*j+1].x, s[2*j+1].y));
            pa[j].w = h2ex2(packh2(s[2*j+1].z, s[2*j+1].w));
        }

        // row sums via tensor core (ones column); exact fp32
        #pragma unroll
        for (int j = 0; j < 4; j++)
            mma16(osum, pa[j], ones_b, ones_b);

        // O += P V
        #pragma unroll
        for (int j = 0; j < 4; j++) {
            #pragma unroll
            for (int np = 0; np < 4; np++) {
                uint4 vv = *(const uint4*)&Vs[(j*4 + np)*128 + lane*4];
                mma16(o[2*np],   pa[j], vv.x, vv.y);
                mma16(o[2*np+1], pa[j], vv.z, vv.w);
            }
        }
    }

    // broadcast row sums from quad lane 0 (column 0 of osum)
    const float llo = __shfl_sync(0xffffffffu, osum.x, (lane >> 2) * 4);
    const float lhi = __shfl_sync(0xffffffffu, osum.z, (lane >> 2) * 4);
    const float ilo = 1.f / llo, ihi = 1.f / lhi;

    // epilogue: scale + FA2 pack -> fp16 A-frags of OF
    const int rowtile = b*128 + (q0>>4) + wid;
    #pragma unroll
    for (int j = 0; j < 4; j++) {
        uint4 ov;
        ov.x = packh2(o[2*j].x   * ilo, o[2*j].y   * ilo);
        ov.y = packh2(o[2*j].z   * ihi, o[2*j].w   * ihi);
        ov.z = packh2(o[2*j+1].x * ilo, o[2*j+1].y * ilo);
        ov.w = packh2(o[2*j+1].z * ihi, o[2*j+1].w * ihi);
        *(uint4*)&g_OF16u[((size_t)rowtile*32 + h*4 + j)*128 + lane*4] = ov;
    }
}

// ---------------------------------------------------------------------------
extern "C" void kernel_launch(void* const* d_in, const int* in_sizes, int n_in,
                              void* d_out, int out_size)
{
    const float* x  = (const float*)d_in[0];
    const float* Wq = (const float*)d_in[1];
    const float* Wk = (const float*)d_in[2];
    const float* Wv = (const float*)d_in[3];
    const float* bq = (const float*)d_in[4];
    const float* bk = (const float*)d_in[5];
    const float* bv = (const float*)d_in[6];
    const float* Wo = (const float*)d_in[7];
    const float* bo = (const float*)d_in[8];
    float* out = (float*)d_out;

    (void)in_sizes; (void)n_in; (void)out_size;

    static int smem_set = 0;
    if (!smem_set) {
        cudaFuncSetAttribute(qkv_proj_kernel,
            cudaFuncAttributeMaxDynamicSharedMemorySize, GEMM_SMEM_BYTES);
        cudaFuncSetAttribute(attn_kernel,
            cudaFuncAttributeMaxDynamicSharedMemorySize, ATTN_SMEM_BYTES);
        cudaFuncSetAttribute(out_proj_kernel,
            cudaFuncAttributeMaxDynamicSharedMemorySize, GEMM_SMEM_BYTES);
        smem_set = 1;
    }

    xw_transform_kernel<<<1536, 256>>>(x, Wq, Wk, Wv, Wo);
    qkv_proj_kernel<<<dim3(DM_/128, MTOT/128, 3), 256, GEMM_SMEM_BYTES>>>(bq, bk, bv);
    attn_kernel<<<dim3(S_/128, BH_), 256, ATTN_SMEM_BYTES>>>();
    out_proj_kernel<<<dim3(DM_/128, MTOT/128), 256, GEMM_SMEM_BYTES>>>(bo, out);
}

// round 16
// speedup vs baseline: 1.0851x; 1.0720x over previous
#include <cuda_runtime.h>
#include <cuda_fp16.h>
#include <cstdint>

#define B_   2
#define S_   2048
#define H_   8
#define DH_  64
#define DM_  512
#define BH_  (B_*H_)
#define MTOT (B_*S_)   // 4096

// exp(s/8) = exp2(s * 0.125 * log2(e)); folded into Q at qkv epilogue
#define EXP_C 0.18033688011112042f

// fp16 fragment-order scratch (uint32 = 2 halves)
__device__ uint32_t g_xF16u[256*32*128];
__device__ uint32_t g_WF16u[4*32*32*128];
__device__ uint32_t g_OF16u[256*32*128];
__device__ uint16_t g_QF16[16*128*4*256];
__device__ uint16_t g_KF16[16*32*4*4*256];
__device__ uint16_t g_VF16[16*32*4*4*256];

__device__ __forceinline__ uint32_t packh2(float lo, float hi) {
    uint32_t r;
    asm("cvt.rn.f16x2.f32 %0, %1, %2;" : "=r"(r) : "f"(hi), "f"(lo));
    return r;
}
__device__ __forceinline__ uint32_t h2ex2(uint32_t x) {
    uint32_t r;
    asm("ex2.approx.f16x2 %0, %1;" : "=r"(r) : "r"(x));
    return r;
}
__device__ __forceinline__ void mma16(float4& d, const uint4& a, uint32_t b0, uint32_t b1) {
    asm volatile(
        "mma.sync.aligned.m16n8k16.row.col.f32.f16.f16.f32 "
        "{%0,%1,%2,%3}, {%4,%5,%6,%7}, {%8,%9}, {%0,%1,%2,%3};"
        : "+f"(d.x), "+f"(d.y), "+f"(d.z), "+f"(d.w)
        : "r"(a.x), "r"(a.y), "r"(a.z), "r"(a.w), "r"(b0), "r"(b1));
}
__device__ __forceinline__ void cpa16(uint32_t smem, const void* gmem) {
    asm volatile("cp.async.cg.shared.global [%0], [%1], 16;" :: "r"(smem), "l"(gmem));
}
__device__ __forceinline__ void cpa_commit() {
    asm volatile("cp.async.commit_group;");
}
template<int N> __device__ __forceinline__ void cpa_wait() {
    asm volatile("cp.async.wait_group %0;" :: "n"(N));
}

// ---------------------------------------------------------------------------
// Merged transform: x -> A-frags (tasks 0..8191), W -> paired B-frags (8192..12287)
// ---------------------------------------------------------------------------
__global__ __launch_bounds__(256) void xw_transform_kernel(
    const float* __restrict__ x,
    const float* __restrict__ Wq, const float* __restrict__ Wk,
    const float* __restrict__ Wv, const float* __restrict__ Wo)
{
    const int task = blockIdx.x * 8 + (threadIdx.x >> 5);
    const int lane = threadIdx.x & 31;
    if (task < 8192) {
        const int rt = task >> 5, ks = task & 31;
        const int r0 = rt*16 + (lane >> 2);
        const int k0 = ks*16 + 2*(lane & 3);
        float2 a = *(const float2*)&x[(size_t)r0*DM_ + k0];
        float2 b = *(const float2*)&x[(size_t)(r0+8)*DM_ + k0];
        float2 c = *(const float2*)&x[(size_t)r0*DM_ + k0 + 8];
        float2 d = *(const float2*)&x[(size_t)(r0+8)*DM_ + k0 + 8];
        uint4 v;
        v.x = packh2(a.x, a.y);
        v.y = packh2(b.x, b.y);
        v.z = packh2(c.x, c.y);
        v.w = packh2(d.x, d.y);
        *(uint4*)&g_xF16u[(size_t)task*128 + lane*4] = v;
    } else {
        const int wtask = task - 8192;
        const int z = wtask >> 10, ks = (wtask >> 5) & 31, np = wtask & 31;
        const int k0 = ks*16 + 2*(lane & 3);
        const int n0 = np*16 + (lane >> 2);
        auto ldw = [&](int k, int n) -> float {
            if (z == 3) return Wo[(size_t)k*DM_ + n];
            const float* Wz = (z == 0) ? Wq : (z == 1) ? Wk : Wv;
            return Wz[((size_t)(n >> 6)*DM_ + k)*DH_ + (n & 63)];
        };
        uint4 v;
        v.x = packh2(ldw(k0,   n0),   ldw(k0+1, n0));
        v.y = packh2(ldw(k0+8, n0),   ldw(k0+9, n0));
        v.z = packh2(ldw(k0,   n0+8), ldw(k0+1, n0+8));
        v.w = packh2(ldw(k0+8, n0+8), ldw(k0+9, n0+8));
        *(uint4*)&g_WF16u[(size_t)wtask*128 + lane*4] = v;
    }
}

// ---------------------------------------------------------------------------
// QKV fp16 frag-order scatter. Q gets EXP_C folded in.
// ---------------------------------------------------------------------------
__device__ __forceinline__ void store_qkv16(int z, float val, int row, int col)
{
    int b = row >> 11, s = row & (S_-1);
    int h = col >> 6, d = col & 63;
    int bh = b*8 + h;
    if (z == 0) val *= EXP_C;
    uint16_t hv = __half_as_ushort(__float2half_rn(val));
    if (z == 0) {
        int qtile = s >> 4, r = s & 15, dstep = d >> 4, k = d & 15;
        int lane = (r & 7)*4 + ((k & 7) >> 1);
        int reg  = ((r >> 3) & 1) + (((k >> 3) & 1) << 1);
        size_t u32i = (((size_t)(bh*128 + qtile))*4 + dstep)*128 + lane*4 + reg;
        g_QF16[u32i*2 + (k & 1)] = hv;
    } else if (z == 1) {
        int kt = s >> 6, nt = (s & 63) >> 3, n = s & 7, dstep = d >> 4, k = d & 15;
        int lane = n*4 + ((k & 7) >> 1);
        size_t u32i = ((((size_t)(bh*32 + kt))*4 + dstep)*4 + (nt >> 1))*128
                    + lane*4 + (nt & 1)*2 + ((k >> 3) & 1);
        g_KF16[u32i*2 + (k & 1)] = hv;
    } else {
        int kt = s >> 6, kstep = (s & 63) >> 4, k = s & 15, nt = d >> 3, n = d & 7;
        int lane = n*4 + ((k & 7) >> 1);
        size_t u32i = ((((size_t)(bh*32 + kt))*4 + kstep)*4 + (nt >> 1))*128
                    + lane*4 + (nt & 1)*2 + ((k >> 3) & 1);
        g_VF16[u32i*2 + (k & 1)] = hv;
    }
}

// ---------------------------------------------------------------------------
// fp16 GEMM mainloop, parametrized by MT (m16-tiles per warp).
// CTA tile = (32*MT) x 128, chunk K=32, 3-stage cp.async ring, one sync/chunk.
// MT=2: 64x128 tiles, ~80 regs, 3 CTAs/SM, stage = 4KB A + 8KB B.
// ---------------------------------------------------------------------------
template<int MT, typename EpiF>
__device__ __forceinline__ void gemm16_body(
    const uint32_t* __restrict__ Asrc,
    const uint32_t* __restrict__ Bsrc,
    int rt0, int np0, EpiF epi)
{
    constexpr int RT = 2*MT;                   // rowtiles per CTA
    constexpr int LOG2RT = (MT == 2) ? 2 : 3;
    constexpr uint32_t ABYTES = 2048u*MT;      // A bytes per stage
    constexpr uint32_t STAGE  = ABYTES + 8192; // + B 8KB

    extern __shared__ float smf[];
    uint32_t* smu = (uint32_t*)smf;
    const uint32_t sbase = (uint32_t)__cvta_generic_to_shared(smf);

    const int tid  = threadIdx.x;
    const int lane = tid & 31;
    const int wid  = tid >> 5;
    const int wm   = wid >> 2, wn = wid & 3;

    float4 c[MT][4];
    #pragma unroll
    for (int i = 0; i < MT; i++)
        #pragma unroll
        for (int j = 0; j < 4; j++) c[i][j] = make_float4(0.f,0.f,0.f,0.f);

    auto stage = [&](int chunk, int st) {
        const int ks0 = chunk * 2;
        const uint32_t s0 = sbase + (uint32_t)st * STAGE;
        #pragma unroll
        for (int c2 = 0; c2 < MT/2; c2++) {
            int seg = tid + 256*c2;
            int bb = seg >> 5, w = seg & 31;
            cpa16(s0 + (uint32_t)seg*16,
                  &Asrc[((size_t)(rt0 + (bb & (RT-1)))*32 + ks0 + (bb >> LOG2RT))*128 + w*4]);
        }
        #pragma unroll
        for (int c2 = 0; c2 < 2; c2++) {
            int seg = tid + 256*c2;
            int bb = seg >> 5, w = seg & 31;
            cpa16(s0 + ABYTES + (uint32_t)seg*16,
                  &Bsrc[((size_t)(ks0 + (bb >> 3))*32 + np0 + (bb & 7))*128 + w*4]);
        }
        cpa_commit();
    };

    stage(0, 0);
    stage(1, 1);
    for (int ch = 0; ch < 16; ch++) {
        if (ch < 15) cpa_wait<1>(); else cpa_wait<0>();
        __syncthreads();
        if (ch + 2 < 16) stage(ch + 2, (ch + 2) % 3);
        const uint32_t* As = smu + (ch % 3) * (STAGE/4);
        const uint32_t* Bs = As + ABYTES/4;
        #pragma unroll
        for (int step = 0; step < 2; step++) {
            uint4 af[MT];
            #pragma unroll
            for (int mt = 0; mt < MT; mt++)
                af[mt] = *(const uint4*)&As[(step*RT + wm*MT + mt)*128 + lane*4];
            #pragma unroll
            for (int np = 0; np < 2; np++) {
                uint4 bb = *(const uint4*)&Bs[(step*8 + wn*2 + np)*128 + lane*4];
                #pragma unroll
                for (int mt = 0; mt < MT; mt++) {
                    mma16(c[mt][2*np],   af[mt], bb.x, bb.y);
                    mma16(c[mt][2*np+1], af[mt], bb.z, bb.w);
                }
            }
        }
    }
    epi(c, wm, wn, lane);
}

#define GEMM_SMEM_BYTES (3*(2048*2 + 8192))   // MT=2: 36864

__global__ __launch_bounds__(256, 3) void qkv_proj_kernel(
    const float* __restrict__ bq, const float* __restrict__ bk, const float* __restrict__ bv)
{
    const int z  = blockIdx.z;
    const float* bias = (z == 0) ? bq : (z == 1) ? bk : bv;
    const int n0 = blockIdx.x * 128;
    const int m0 = blockIdx.y * 64;

    gemm16_body<2>(g_xF16u, &g_WF16u[(size_t)z*32*32*128], m0 >> 4, n0 >> 4,
        [&](float4 (&c)[2][4], int wm, int wn, int lane) {
            const int g = lane >> 2, t = lane & 3;
            #pragma unroll
            for (int mt = 0; mt < 2; mt++) {
                int r1 = m0 + wm*32 + mt*16 + g;
                #pragma unroll
                for (int nt = 0; nt < 4; nt++) {
                    int c1 = n0 + wn*32 + nt*8 + 2*t;
                    float b0 = bias[c1], b1 = bias[c1+1];
                    store_qkv16(z, c[mt][nt].x + b0, r1,   c1);
                    store_qkv16(z, c[mt][nt].y + b1, r1,   c1+1);
                    store_qkv16(z, c[mt][nt].z + b0, r1+8, c1);
                    store_qkv16(z, c[mt][nt].w + b1, r1+8, c1+1);
                }
            }
        });
}

__global__ __launch_bounds__(256, 3) void out_proj_kernel(
    const float* __restrict__ bo, float* __restrict__ out)
{
    const int n0 = blockIdx.x * 128;
    const int m0 = blockIdx.y * 64;

    gemm16_body<2>(g_OF16u, &g_WF16u[(size_t)3*32*32*128], m0 >> 4, n0 >> 4,
        [&](float4 (&c)[2][4], int wm, int wn, int lane) {
            const int g = lane >> 2, t = lane & 3;
            #pragma unroll
            for (int mt = 0; mt < 2; mt++) {
                int mlo = m0 + wm*32 + mt*16 + g;
                int mhi = mlo + 8;
                #pragma unroll
                for (int nt = 0; nt < 4; nt++) {
                    int col = n0 + wn*32 + nt*8 + 2*t;
                    float b0 = bo[col], b1 = bo[col+1];
                    *(float2*)&out[(size_t)mlo*DM_ + col] =
                        make_float2(c[mt][nt].x + b0, c[mt][nt].y + b1);
                    *(float2*)&out[(size_t)mhi*DM_ + col] =
                        make_float2(c[mt][nt].z + b0, c[mt][nt].w + b1);
                }
            }
        });
}

// ---------------------------------------------------------------------------
// Flash attention (R13-passing version): fp16 k16 mma.sync, paired B-frags,
// EXP_C pre-folded into Q, fp16x2 exp, tensor-core row sums, 3-stage ring.
// ---------------------------------------------------------------------------
#define ATTN_SMEM_BYTES (3*16384)   // 48 KB

__global__ __launch_bounds__(256, 2) void attn_kernel()
{
    extern __shared__ float smf[];
    uint32_t* smu = (uint32_t*)smf;
    const uint32_t sbase = (uint32_t)__cvta_generic_to_shared(smf);

    const int tid  = threadIdx.x;
    const int lane = tid & 31;
    const int wid  = tid >> 5;
    const int q0 = blockIdx.x * 128;
    const int bh = blockIdx.y;
    const int b  = bh >> 3, h = bh & 7;

    uint4 qf[4];
    {
        const uint32_t* QFu = (const uint32_t*)g_QF16;
        const size_t qbase = ((size_t)(bh*128 + (q0>>4) + wid)) * 4 * 128;
        #pragma unroll
        for (int step = 0; step < 4; step++)
            qf[step] = *(const uint4*)&QFu[qbase + step*128 + lane*4];
    }

    float4 o[8];
    #pragma unroll
    for (int nt = 0; nt < 8; nt++) o[nt] = make_float4(0.f,0.f,0.f,0.f);
    float4 osum = make_float4(0.f,0.f,0.f,0.f);
    const uint32_t ones_b = (lane < 4) ? 0x3C003C00u : 0u;

    const uint32_t* KFu = (const uint32_t*)g_KF16 + (size_t)bh*32*2048;
    const uint32_t* VFu = (const uint32_t*)g_VF16 + (size_t)bh*32*2048;

    auto stage = [&](int kt, int st) {
        const uint32_t s0 = sbase + (uint32_t)(st * 16384);
        const uint32_t* Ksrc = KFu + (size_t)kt * 2048;
        const uint32_t* Vsrc = VFu + (size_t)kt * 2048;
        #pragma unroll
        for (int c2 = 0; c2 < 2; c2++) {
            int seg = tid + 256*c2;
            cpa16(s0 + (uint32_t)seg*16,        Ksrc + seg*4);
            cpa16(s0 + 8192 + (uint32_t)seg*16, Vsrc + seg*4);
        }
        cpa_commit();
    };

    stage(0, 0);
    stage(1, 1);
    for (int kt = 0; kt < 32; kt++) {
        if (kt < 31) cpa_wait<1>(); else cpa_wait<0>();
        __syncthreads();
        if (kt + 2 < 32) stage(kt + 2, (kt + 2) % 3);
        const uint32_t* Ks = smu + (kt % 3) * 4096;
        const uint32_t* Vs = Ks + 2048;

        // S = Q K^T (log2-domain)
        float4 s[8];
        #pragma unroll
        for (int nt = 0; nt < 8; nt++) s[nt] = make_float4(0.f,0.f,0.f,0.f);
        #pragma unroll
        for (int step = 0; step < 4; step++) {
            #pragma unroll
            for (int np = 0; np < 4; np++) {
                uint4 kk = *(const uint4*)&Ks[(step*4 + np)*128 + lane*4];
                mma16(s[2*np],   qf[step], kk.x, kk.y);
                mma16(s[2*np+1], qf[step], kk.z, kk.w);
            }
        }

        // pack then exp2 (fp16x2) -> P A-frags directly
        uint4 pa[4];
        #pragma unroll
        for (int j = 0; j < 4; j++) {
            pa[j].x = h2ex2(packh2(s[2*j].x,   s[2*j].y));
            pa[j].y = h2ex2(packh2(s[2*j].z,   s[2*j].w));
            pa[j].z = h2ex2(packh2(s[2*j+1].x, s[2*j+1].y));
            pa[j].w = h2ex2(packh2(s[2*j+1].z, s[2*j+1].w));
        }

        // row sums via tensor core (ones column)
        #pragma unroll
        for (int j = 0; j < 4; j++)
            mma16(osum, pa[j], ones_b, ones_b);

        // O += P V
        #pragma unroll
        for (int j = 0; j < 4; j++) {
            #pragma unroll
            for (int np = 0; np < 4; np++) {
                uint4 vv = *(const uint4*)&Vs[(j*4 + np)*128 + lane*4];
                mma16(o[2*np],   pa[j], vv.x, vv.y);
                mma16(o[2*np+1], pa[j], vv.z, vv.w);
            }
        }
    }

    const float llo = __shfl_sync(0xffffffffu, osum.x, (lane >> 2) * 4);
    const float lhi = __shfl_sync(0xffffffffu, osum.z, (lane >> 2) * 4);
    const float ilo = 1.f / llo, ihi = 1.f / lhi;

    const int rowtile = b*128 + (q0>>4) + wid;
    #pragma unroll
    for (int j = 0; j < 4; j++) {
        uint4 ov;
        ov.x = packh2(o[2*j].x   * ilo, o[2*j].y   * ilo);
        ov.y = packh2(o[2*j].z   * ihi, o[2*j].w   * ihi);
        ov.z = packh2(o[2*j+1].x * ilo, o[2*j+1].y * ilo);
        ov.w = packh2(o[2*j+1].z * ihi, o[2*j+1].w * ihi);
        *(uint4*)&g_OF16u[((size_t)rowtile*32 + h*4 + j)*128 + lane*4] = ov;
    }
}

// ---------------------------------------------------------------------------
extern "C" void kernel_launch(void* const* d_in, const int* in_sizes, int n_in,
                              void* d_out, int out_size)
{
    const float* x  = (const float*)d_in[0];
    const float* Wq = (const float*)d_in[1];
    const float* Wk = (const float*)d_in[2];
    const float* Wv = (const float*)d_in[3];
    const float* bq = (const float*)d_in[4];
    const float* bk = (const float*)d_in[5];
    const float* bv = (const float*)d_in[6];
    const float* Wo = (const float*)d_in[7];
    const float* bo = (const float*)d_in[8];
    float* out = (float*)d_out;

    (void)in_sizes; (void)n_in; (void)out_size;

    static int smem_set = 0;
    if (!smem_set) {
        cudaFuncSetAttribute(qkv_proj_kernel,
            cudaFuncAttributeMaxDynamicSharedMemorySize, GEMM_SMEM_BYTES);
        cudaFuncSetAttribute(attn_kernel,
            cudaFuncAttributeMaxDynamicSharedMemorySize, ATTN_SMEM_BYTES);
        cudaFuncSetAttribute(out_proj_kernel,
            cudaFuncAttributeMaxDynamicSharedMemorySize, GEMM_SMEM_BYTES);
        smem_set = 1;
    }

    xw_transform_kernel<<<1536, 256>>>(x, Wq, Wk, Wv, Wo);
    qkv_proj_kernel<<<dim3(DM_/128, MTOT/64, 3), 256, GEMM_SMEM_BYTES>>>(bq, bk, bv);
    attn_kernel<<<dim3(S_/128, BH_), 256, ATTN_SMEM_BYTES>>>();
    out_proj_kernel<<<dim3(DM_/128, MTOT/64), 256, GEMM_SMEM_BYTES>>>(bo, out);
}